// round 16
// baseline (speedup 1.0000x reference)
#include <cuda_runtime.h>
#include <cuda_bf16.h>
#include <math.h>
#include <cstdint>

#define D_MODEL 1024
#define N_HEADS 16
#define HD      64
#define BATCH   2
#define SEQ     2048
#define ROWS    (BATCH*SEQ)      // 4096
#define QKV_N   (3*D_MODEL)      // 3072
#define LN_EPS  1e-6f

// Scratch (device-global: no runtime allocation allowed)
__device__ float g_qkv[(size_t)ROWS * QKV_N];              // 48 MB fp32 qkv
// bf16 hi/lo planes for GEMMs. Activations [M][K]; weights TRANSPOSED [N][K].
__device__ __nv_bfloat16 g_xh[(size_t)ROWS * D_MODEL];
__device__ __nv_bfloat16 g_xl[(size_t)ROWS * D_MODEL];
__device__ __nv_bfloat16 g_wqh[(size_t)QKV_N * D_MODEL];
__device__ __nv_bfloat16 g_wql[(size_t)QKV_N * D_MODEL];
__device__ __nv_bfloat16 g_woh[(size_t)D_MODEL * D_MODEL];
__device__ __nv_bfloat16 g_wol[(size_t)D_MODEL * D_MODEL];
__device__ __nv_bfloat16 g_cth[(size_t)ROWS * D_MODEL];    // ctx planes
__device__ __nv_bfloat16 g_ctl[(size_t)ROWS * D_MODEL];
// attention operand planes (bf16, packed as u32 pairs)
__device__ uint32_t g_kph[(size_t)ROWS * D_MODEL / 2];     // K post-LN hi
__device__ uint32_t g_kpl[(size_t)ROWS * D_MODEL / 2];     // K post-LN lo
__device__ uint32_t g_vth[(size_t)ROWS * D_MODEL / 2];     // V^T hi  [b,h][d][s]
__device__ uint32_t g_vtl[(size_t)ROWS * D_MODEL / 2];     // V^T lo

__device__ __forceinline__ uint32_t smem_u32(const void* p) {
    return (uint32_t)__cvta_generic_to_shared(p);
}

__device__ __forceinline__ void mma_bf16(float* d, const uint32_t* a, const uint32_t* b) {
    asm volatile(
        "mma.sync.aligned.m16n8k16.row.col.f32.bf16.bf16.f32 "
        "{%0,%1,%2,%3}, {%4,%5,%6,%7}, {%8,%9}, {%0,%1,%2,%3};\n"
        : "+f"(d[0]), "+f"(d[1]), "+f"(d[2]), "+f"(d[3])
        : "r"(a[0]), "r"(a[1]), "r"(a[2]), "r"(a[3]), "r"(b[0]), "r"(b[1]));
}
__device__ __forceinline__ float bf16round(float x) {
    return __bfloat162float(__float2bfloat16_rn(x));
}
__device__ __forceinline__ uint32_t pack_bf16(float a, float b) {
    uint16_t ua = __bfloat16_as_ushort(__float2bfloat16_rn(a));
    uint16_t ub = __bfloat16_as_ushort(__float2bfloat16_rn(b));
    return (uint32_t)ua | ((uint32_t)ub << 16);
}

// ---------------------------------------------------------------------------
// Activation split: X fp32 [M][K] -> bf16 hi/lo planes. 4 elems/thread.
// ---------------------------------------------------------------------------
__global__ __launch_bounds__(256)
void xsplit_kernel(const float* __restrict__ X, __nv_bfloat16* __restrict__ Xh,
                   __nv_bfloat16* __restrict__ Xl, int n4) {
    int i = blockIdx.x * blockDim.x + threadIdx.x;
    if (i >= n4) return;
    float4 v = ((const float4*)X)[i];
    float hx = bf16round(v.x), hy = bf16round(v.y);
    float hz = bf16round(v.z), hw = bf16round(v.w);
    uint32_t* H = (uint32_t*)Xh;
    uint32_t* L = (uint32_t*)Xl;
    H[2 * i]     = pack_bf16(hx, hy);
    H[2 * i + 1] = pack_bf16(hz, hw);
    L[2 * i]     = pack_bf16(v.x - hx, v.y - hy);
    L[2 * i + 1] = pack_bf16(v.z - hz, v.w - hw);
}

// ---------------------------------------------------------------------------
// Weight transpose + split: W fp32 [Kd][Nd] -> Th/Tl bf16 [Nd][Kd].
// ---------------------------------------------------------------------------
__global__ __launch_bounds__(256)
void trsplit_kernel(const float* __restrict__ W, __nv_bfloat16* __restrict__ Th,
                    __nv_bfloat16* __restrict__ Tl, int Kd, int Nd) {
    __shared__ float T[32][33];
    const int tid = threadIdx.x;
    const int tx = tid & 31, ty = tid >> 5;
    const int k0 = blockIdx.y * 32, n0 = blockIdx.x * 32;
#pragma unroll
    for (int r = 0; r < 4; r++)
        T[ty + r * 8][tx] = W[(size_t)(k0 + ty + r * 8) * Nd + n0 + tx];
    __syncthreads();
#pragma unroll
    for (int i = 0; i < 2; i++) {
        int idx = tid + i * 256;
        int nl = idx >> 4, kp = idx & 15;
        float v0 = T[kp * 2][nl], v1 = T[kp * 2 + 1][nl];
        float h0 = bf16round(v0), h1 = bf16round(v1);
        size_t e = (size_t)(n0 + nl) * Kd + k0 + kp * 2;
        ((uint32_t*)Th)[e >> 1] = pack_bf16(h0, h1);
        ((uint32_t*)Tl)[e >> 1] = pack_bf16(v0 - h0, v1 - h1);
    }
}

// ---------------------------------------------------------------------------
// V transpose + split: qkv v-slice -> VT planes [(b*16+h)*64+d][s] bf16 hi/lo.
// ---------------------------------------------------------------------------
__global__ __launch_bounds__(256)
void vtsplit_kernel(const float* __restrict__ qkv,
                    uint32_t* __restrict__ VTh, uint32_t* __restrict__ VTl) {
    __shared__ float T[32][33];
    const int tid = threadIdx.x;
    const int s0 = blockIdx.x * 32;
    const int d0 = blockIdx.y * 32;
    const int bh = blockIdx.z;
    const int b  = bh / N_HEADS;
    const int h  = bh % N_HEADS;
    const int tx = tid & 31, ty = tid >> 5;
#pragma unroll
    for (int r = 0; r < 4; r++) {
        int si = ty + r * 8;
        T[si][tx] = qkv[((size_t)(b * SEQ + s0 + si)) * QKV_N + 2 * D_MODEL + h * HD + d0 + tx];
    }
    __syncthreads();
#pragma unroll
    for (int i = 0; i < 2; i++) {
        int idx = tid + i * 256;           // 0..511
        int dl = idx >> 4, sp = idx & 15;
        float v0 = T[sp * 2][dl], v1 = T[sp * 2 + 1][dl];
        float h0 = bf16round(v0), h1 = bf16round(v1);
        size_t u = (size_t)(bh * HD + d0 + dl) * (SEQ / 2) + (s0 >> 1) + sp;
        VTh[u] = pack_bf16(h0, h1);
        VTl[u] = pack_bf16(v0 - h0, v1 - h1);
    }
}

// ===========================================================================
// 3xBF16 GEMM (validated R11/R13): C[M][N] = A[M][K] @ B^T, pre-split planes.
// ===========================================================================
#define BM 128
#define BN 128
#define BKE 32
#define RSTR 20
#define PLANE (128 * RSTR)
#define OFF_AL PLANE
#define OFF_BH (2 * PLANE)
#define OFF_BL (3 * PLANE)
#define STAGE_U32 (4 * PLANE)
#define GEMM_SMEM_BYTES (2 * STAGE_U32 * 4)   // 81920

__global__ __launch_bounds__(256, 2)
void gemm_bf16x3_kernel(const __nv_bfloat16* __restrict__ Ah, const __nv_bfloat16* __restrict__ Al,
                        const __nv_bfloat16* __restrict__ Bh, const __nv_bfloat16* __restrict__ Bl,
                        float* __restrict__ C, int M, int N, int K) {
    extern __shared__ uint32_t smu[];

    const int tid  = threadIdx.x;
    const int lane = tid & 31;
    const int warp = tid >> 5;
    const int warp_m = warp & 1;
    const int warp_n = warp >> 1;
    const int t4  = lane >> 2;
    const int tm4 = lane & 3;
    const int bm = blockIdx.y * BM;
    const int bn = blockIdx.x * BN;

    float acc[4][4][4];
#pragma unroll
    for (int mt = 0; mt < 4; mt++)
#pragma unroll
        for (int nt = 0; nt < 4; nt++)
#pragma unroll
            for (int r = 0; r < 4; r++) acc[mt][nt][r] = 0.f;

    const int nk = K / BKE;

    auto prefetch = [&](int buf, int kt) {
        const int k0 = kt * BKE;
        const int sb = buf * STAGE_U32;
#pragma unroll
        for (int l = 0; l < 4; l++) {
            int c = tid + l * 256;
            int plane = c >> 9, cc = c & 511;
            int m = cc >> 2, ch = cc & 3;
            const __nv_bfloat16* src = (plane ? Al : Ah) + (size_t)(bm + m) * K + k0 + ch * 8;
            uint32_t dst = smem_u32(&smu[sb + (plane ? OFF_AL : 0) + m * RSTR + ch * 4]);
            asm volatile("cp.async.cg.shared.global [%0], [%1], 16;\n"
                         :: "r"(dst), "l"(src));
        }
#pragma unroll
        for (int l = 0; l < 4; l++) {
            int c = tid + l * 256;
            int plane = c >> 9, cc = c & 511;
            int n = cc >> 2, ch = cc & 3;
            const __nv_bfloat16* src = (plane ? Bl : Bh) + (size_t)(bn + n) * K + k0 + ch * 8;
            uint32_t dst = smem_u32(&smu[sb + (plane ? OFF_BL : OFF_BH) + n * RSTR + ch * 4]);
            asm volatile("cp.async.cg.shared.global [%0], [%1], 16;\n"
                         :: "r"(dst), "l"(src));
        }
        asm volatile("cp.async.commit_group;\n");
    };

    prefetch(0, 0);

    for (int kt = 0; kt < nk; kt++) {
        const int buf = kt & 1;
        if (kt + 1 < nk) {
            prefetch(buf ^ 1, kt + 1);
            asm volatile("cp.async.wait_group 1;\n");
        } else {
            asm volatile("cp.async.wait_group 0;\n");
        }
        __syncthreads();

        const uint32_t* AhU = smu + buf * STAGE_U32;
        const uint32_t* AlU = AhU + OFF_AL;
        const uint32_t* BhU = AhU + OFF_BH;
        const uint32_t* BlU = AhU + OFF_BL;

#pragma unroll
        for (int ks = 0; ks < 2; ks++) {
            const int k0u = ks * 8;
            uint32_t ah[4][4], al[4][4];
#pragma unroll
            for (int mt = 0; mt < 4; mt++) {
                const int rb = warp_m * 64 + mt * 16;
                const int i0 = (rb + t4)     * RSTR + k0u + tm4;
                const int i1 = (rb + 8 + t4) * RSTR + k0u + tm4;
                ah[mt][0] = AhU[i0];     al[mt][0] = AlU[i0];
                ah[mt][1] = AhU[i1];     al[mt][1] = AlU[i1];
                ah[mt][2] = AhU[i0 + 4]; al[mt][2] = AlU[i0 + 4];
                ah[mt][3] = AhU[i1 + 4]; al[mt][3] = AlU[i1 + 4];
            }
            uint32_t bh[4][2], bl[4][2];
#pragma unroll
            for (int nt = 0; nt < 4; nt++) {
                const int nb = warp_n * 32 + nt * 8;
                const int i0 = (nb + t4) * RSTR + k0u + tm4;
                bh[nt][0] = BhU[i0];     bl[nt][0] = BlU[i0];
                bh[nt][1] = BhU[i0 + 4]; bl[nt][1] = BlU[i0 + 4];
            }
#pragma unroll
            for (int mt = 0; mt < 4; mt++)
#pragma unroll
                for (int nt = 0; nt < 4; nt++) {
                    mma_bf16(acc[mt][nt], al[mt], bh[nt]);
                    mma_bf16(acc[mt][nt], ah[mt], bl[nt]);
                    mma_bf16(acc[mt][nt], ah[mt], bh[nt]);
                }
        }
        __syncthreads();
    }

#pragma unroll
    for (int mt = 0; mt < 4; mt++) {
#pragma unroll
        for (int nt = 0; nt < 4; nt++) {
            const int row = bm + warp_m * 64 + mt * 16 + t4;
            const int col = bn + warp_n * 32 + nt * 8 + tm4 * 2;
            float2 v0 = make_float2(acc[mt][nt][0], acc[mt][nt][1]);
            float2 v1 = make_float2(acc[mt][nt][2], acc[mt][nt][3]);
            *(float2*)&C[(size_t)row * N + col]       = v0;
            *(float2*)&C[(size_t)(row + 8) * N + col] = v1;
        }
    }
}

// ---------------------------------------------------------------------------
// LayerNorm (scale-only). which=0: q normalized fp32 in place.
// which=1: k -> pre-split bf16 hi/lo planes (u32 packed).
// ---------------------------------------------------------------------------
__global__ __launch_bounds__(256)
void ln_kernel(float* __restrict__ qkv, const float* __restrict__ q_scale,
               const float* __restrict__ k_scale,
               uint32_t* __restrict__ kh, uint32_t* __restrict__ kl) {
    const int row = blockIdx.x;
    const int which = blockIdx.y;
    const float* scale = which ? k_scale : q_scale;
    float* ptr = qkv + (size_t)row * QKV_N + which * D_MODEL;

    const int tid = threadIdx.x;
    float4 v = ((const float4*)ptr)[tid];
    float sum = v.x + v.y + v.z + v.w;
    float sq  = v.x * v.x + v.y * v.y + v.z * v.z + v.w * v.w;
#pragma unroll
    for (int o = 16; o > 0; o >>= 1) {
        sum += __shfl_xor_sync(0xffffffffu, sum, o);
        sq  += __shfl_xor_sync(0xffffffffu, sq,  o);
    }
    __shared__ float ssum[8], ssq[8];
    const int warp = tid >> 5, lane = tid & 31;
    if (lane == 0) { ssum[warp] = sum; ssq[warp] = sq; }
    __syncthreads();
    if (tid == 0) {
        float a = 0.f, bsum = 0.f;
#pragma unroll
        for (int w = 0; w < 8; w++) { a += ssum[w]; bsum += ssq[w]; }
        ssum[0] = a; ssq[0] = bsum;
    }
    __syncthreads();
    const float mean = ssum[0] * (1.f / D_MODEL);
    const float var  = ssq[0] * (1.f / D_MODEL) - mean * mean;
    const float inv  = rsqrtf(var + LN_EPS);

    const int c = tid * 4;
    float n0 = (v.x - mean) * inv * scale[c];
    float n1 = (v.y - mean) * inv * scale[c + 1];
    float n2 = (v.z - mean) * inv * scale[c + 2];
    float n3 = (v.w - mean) * inv * scale[c + 3];
    if (which == 0) {
        ((float4*)ptr)[tid] = make_float4(n0, n1, n2, n3);
    } else {
        float h0 = bf16round(n0), h1 = bf16round(n1);
        float h2 = bf16round(n2), h3 = bf16round(n3);
        size_t u = (size_t)row * (D_MODEL / 2) + tid * 2;
        kh[u]     = pack_bf16(h0, h1);
        kh[u + 1] = pack_bf16(h2, h3);
        kl[u]     = pack_bf16(n0 - h0, n1 - h1);
        kl[u + 1] = pack_bf16(n2 - h2, n3 - h3);
    }
}

// ===========================================================================
// Flash attention, all-bf16x3 tensor core. Causal.
// CTA: 128 q-rows x (head, batch). 256 threads = 8 warps, warp owns 16 rows.
// K/V tiles of 64 rows double-buffered -> each K/V load now serves 128 q-rows
// (half the global traffic of the 64-row version). Warps whose rows precede
// a k-tile skip its compute (they only join barriers).
// Smem u32 layout: Ph[0,4608) Pl[4608,9216) | K 2x(hi,lo)[9216,18432) |
//                  VT 2x(hi,lo)[18432,27648). 110592 B.
// ===========================================================================
#define KSTR 36                    // u32 per 64-bf16 row (+4 pad)
#define APLANE (64 * KSTR)         // 2304 u32 (one 64-row plane)
#define PPLANE (128 * KSTR)        // 4608 u32 (one 128-row P plane)
#define AOFF_K  (2 * PPLANE)       // 9216
#define AOFF_VT (AOFF_K + 4 * APLANE)  // 18432
#define ATTN_SMEM_BYTES ((AOFF_VT + 4 * APLANE) * 4)   // 110592

__global__ __launch_bounds__(256)
void attn_bf16_kernel(const float* __restrict__ qkv,
                      const uint32_t* __restrict__ Kh, const uint32_t* __restrict__ Kl,
                      const uint32_t* __restrict__ VTh, const uint32_t* __restrict__ VTl,
                      __nv_bfloat16* __restrict__ ctxh, __nv_bfloat16* __restrict__ ctxl) {
    extern __shared__ uint32_t smu[];
    uint32_t* Ph = smu;
    uint32_t* Pl = smu + PPLANE;

    const int qb = blockIdx.x;         // 0..15 (128-row q tile)
    const int h  = blockIdx.y;
    const int b  = blockIdx.z;
    const int tid  = threadIdx.x;
    const int lane = tid & 31;
    const int w    = tid >> 5;         // 0..7
    const int t4   = lane >> 2;
    const int tm4  = lane & 3;
    const int w16  = w * 16;

    const int nkt = 2 * qb + 2;        // k-tiles 0 .. 2*qb+1

    auto prefetch_kv = [&](int buf, int kt) {
        const size_t kgo = ((size_t)(b * SEQ + kt * 64) * D_MODEL + h * HD) / 2;
        const size_t vgo = ((size_t)((b * N_HEADS + h) * HD) * SEQ + (size_t)kt * 64) / 2;
        uint32_t* kd = smu + AOFF_K + buf * 2 * APLANE;
        uint32_t* vd = smu + AOFF_VT + buf * 2 * APLANE;
#pragma unroll
        for (int l = 0; l < 2; l++) {
            int c = tid + l * 256;          // 0..511
            int row = c >> 3, ch = c & 7;
            asm volatile("cp.async.cg.shared.global [%0], [%1], 16;\n"
                :: "r"(smem_u32(&kd[row * KSTR + ch * 4])), "l"(Kh + kgo + (size_t)row * 512 + ch * 4));
            asm volatile("cp.async.cg.shared.global [%0], [%1], 16;\n"
                :: "r"(smem_u32(&kd[APLANE + row * KSTR + ch * 4])), "l"(Kl + kgo + (size_t)row * 512 + ch * 4));
            asm volatile("cp.async.cg.shared.global [%0], [%1], 16;\n"
                :: "r"(smem_u32(&vd[row * KSTR + ch * 4])), "l"(VTh + vgo + (size_t)row * 1024 + ch * 4));
            asm volatile("cp.async.cg.shared.global [%0], [%1], 16;\n"
                :: "r"(smem_u32(&vd[APLANE + row * KSTR + ch * 4])), "l"(VTl + vgo + (size_t)row * 1024 + ch * 4));
        }
        asm volatile("cp.async.commit_group;\n");
    };

    prefetch_kv(0, 0);

    // stage Q fp32 in the P area (stride 68 floats, 128x68 = 8704 <= 9216 u32)
    {
        float* Qs = (float*)smu;
        const float* qbase = qkv + ((size_t)(b * SEQ + qb * 128)) * QKV_N + (size_t)h * HD;
#pragma unroll
        for (int l = 0; l < 8; l++) {
            int c = tid + l * 256;          // 0..2047
            int row = c >> 4, c4 = c & 15;
            float4 v = *(const float4*)(qbase + (size_t)row * QKV_N + c4 * 4);
            *(float4*)&Qs[row * 68 + c4 * 4] = v;
        }
    }
    __syncthreads();

    uint32_t qah[4][4], qal[4][4];
    {
        const float* Qs = (const float*)smu;
#pragma unroll
        for (int ks = 0; ks < 4; ks++) {
            const int j0 = ks * 8 + tm4;
#pragma unroll
            for (int p = 0; p < 4; p++) {
                const int r = w16 + t4 + ((p & 1) ? 8 : 0);
                const int j = j0 + ((p >> 1) ? 4 : 0);
                float v0 = 0.125f * Qs[r * 68 + 2 * j];
                float v1 = 0.125f * Qs[r * 68 + 2 * j + 1];
                float h0 = bf16round(v0), h1 = bf16round(v1);
                qah[ks][p] = pack_bf16(h0, h1);
                qal[ks][p] = pack_bf16(v0 - h0, v1 - h1);
            }
        }
    }
    __syncthreads();   // Q staging done; P area free

    float m0 = -1e30f, m1 = -1e30f, l0 = 0.f, l1 = 0.f;
    float oacc[8][4];
#pragma unroll
    for (int nt = 0; nt < 8; nt++)
#pragma unroll
        for (int r = 0; r < 4; r++) oacc[nt][r] = 0.f;

    for (int kt = 0; kt < nkt; kt++) {
        const int buf = kt & 1;
        asm volatile("cp.async.wait_group 0;\n");
        __syncthreads();
        if (kt + 1 < nkt) prefetch_kv(buf ^ 1, kt + 1);

        // warp active if its highest row (w16+15) reaches this k-tile
        const bool active = (kt * 64) <= (qb * 128 + w16 + 15);
        if (active) {
            const uint32_t* KbH = smu + AOFF_K + buf * 2 * APLANE;
            const uint32_t* KbL = KbH + APLANE;
            const uint32_t* VbH = smu + AOFF_VT + buf * 2 * APLANE;
            const uint32_t* VbL = VbH + APLANE;

            // ---- S = (Q*0.125) @ K^T  (3xBF16, m16n8k16, 4 k-steps) ----
            float s[8][4];
#pragma unroll
            for (int nt = 0; nt < 8; nt++)
#pragma unroll
                for (int r = 0; r < 4; r++) s[nt][r] = 0.f;

#pragma unroll
            for (int ks = 0; ks < 4; ks++) {
                const int k0u = ks * 8;
                uint32_t bh[8][2], bl[8][2];
#pragma unroll
                for (int nt = 0; nt < 8; nt++) {
                    const int i0 = (nt * 8 + t4) * KSTR + k0u + tm4;
                    bh[nt][0] = KbH[i0];     bl[nt][0] = KbL[i0];
                    bh[nt][1] = KbH[i0 + 4]; bl[nt][1] = KbL[i0 + 4];
                }
#pragma unroll
                for (int nt = 0; nt < 8; nt++) {
                    mma_bf16(s[nt], qal[ks], bh[nt]);
                    mma_bf16(s[nt], qah[ks], bl[nt]);
                    mma_bf16(s[nt], qah[ks], bh[nt]);
                }
            }

            // causal mask (global indices) — only near/above the diagonal
            if (kt >= 2 * qb) {
                const int rowg0 = qb * 128 + w16 + t4;
#pragma unroll
                for (int nt = 0; nt < 8; nt++) {
                    const int colg = kt * 64 + nt * 8 + tm4 * 2;
                    if (colg     > rowg0)     s[nt][0] = -1e30f;
                    if (colg + 1 > rowg0)     s[nt][1] = -1e30f;
                    if (colg     > rowg0 + 8) s[nt][2] = -1e30f;
                    if (colg + 1 > rowg0 + 8) s[nt][3] = -1e30f;
                }
            }

            // ---- online softmax (fp32 exact) ----
            float rm0 = -1e30f, rm1 = -1e30f;
#pragma unroll
            for (int nt = 0; nt < 8; nt++) {
                rm0 = fmaxf(rm0, fmaxf(s[nt][0], s[nt][1]));
                rm1 = fmaxf(rm1, fmaxf(s[nt][2], s[nt][3]));
            }
#pragma unroll
            for (int o = 1; o <= 2; o <<= 1) {
                rm0 = fmaxf(rm0, __shfl_xor_sync(0xffffffffu, rm0, o));
                rm1 = fmaxf(rm1, __shfl_xor_sync(0xffffffffu, rm1, o));
            }
            const float nm0 = fmaxf(m0, rm0);
            const float nm1 = fmaxf(m1, rm1);
            const float c0 = expf(m0 - nm0);
            const float c1 = expf(m1 - nm1);
            float rs0 = 0.f, rs1 = 0.f;
#pragma unroll
            for (int nt = 0; nt < 8; nt++) {
                s[nt][0] = expf(s[nt][0] - nm0);
                s[nt][1] = expf(s[nt][1] - nm0);
                s[nt][2] = expf(s[nt][2] - nm1);
                s[nt][3] = expf(s[nt][3] - nm1);
                rs0 += s[nt][0] + s[nt][1];
                rs1 += s[nt][2] + s[nt][3];
            }
#pragma unroll
            for (int o = 1; o <= 2; o <<= 1) {
                rs0 += __shfl_xor_sync(0xffffffffu, rs0, o);
                rs1 += __shfl_xor_sync(0xffffffffu, rs1, o);
            }
            l0 = l0 * c0 + rs0;  m0 = nm0;
            l1 = l1 * c1 + rs1;  m1 = nm1;
#pragma unroll
            for (int nt = 0; nt < 8; nt++) {
                oacc[nt][0] *= c0; oacc[nt][1] *= c0;
                oacc[nt][2] *= c1; oacc[nt][3] *= c1;
            }

            // ---- P split hi/lo, packed STS (own 16-row slice) ----
#pragma unroll
            for (int nt = 0; nt < 8; nt++) {
                const int i0 = (w16 + t4)     * KSTR + nt * 4 + tm4;
                const int i1 = (w16 + t4 + 8) * KSTR + nt * 4 + tm4;
                float h0 = bf16round(s[nt][0]), h1 = bf16round(s[nt][1]);
                float h2 = bf16round(s[nt][2]), h3 = bf16round(s[nt][3]);
                Ph[i0] = pack_bf16(h0, h1);
                Pl[i0] = pack_bf16(s[nt][0] - h0, s[nt][1] - h1);
                Ph[i1] = pack_bf16(h2, h3);
                Pl[i1] = pack_bf16(s[nt][2] - h2, s[nt][3] - h3);
            }
            __syncwarp();

            // ---- O += P @ V^T  (3xBF16) ----
#pragma unroll
            for (int ks = 0; ks < 4; ks++) {
                const int j0 = ks * 8 + tm4;
                const int r0i = (w16 + t4) * KSTR;
                const int r1i = (w16 + t4 + 8) * KSTR;
                uint32_t pah[4], pal[4];
                pah[0] = Ph[r0i + j0];     pal[0] = Pl[r0i + j0];
                pah[1] = Ph[r1i + j0];     pal[1] = Pl[r1i + j0];
                pah[2] = Ph[r0i + j0 + 4]; pal[2] = Pl[r0i + j0 + 4];
                pah[3] = Ph[r1i + j0 + 4]; pal[3] = Pl[r1i + j0 + 4];
#pragma unroll
                for (int nt = 0; nt < 8; nt++) {
                    const int i0 = (nt * 8 + t4) * KSTR + ks * 8 + tm4;
                    uint32_t vh[2], vl[2];
                    vh[0] = VbH[i0];     vl[0] = VbL[i0];
                    vh[1] = VbH[i0 + 4]; vl[1] = VbL[i0 + 4];
                    mma_bf16(oacc[nt], pal, vh);
                    mma_bf16(oacc[nt], pah, vl);
                    mma_bf16(oacc[nt], pah, vh);
                }
            }
            __syncwarp();
        }
    }

    // epilogue: normalize, split to bf16 hi/lo ctx planes
    const float i0 = 1.f / l0, i1 = 1.f / l1;
    const size_t r0 = (size_t)(b * SEQ + qb * 128 + w16 + t4) * D_MODEL;
    const size_t r1 = (size_t)(b * SEQ + qb * 128 + w16 + t4 + 8) * D_MODEL;
#pragma unroll
    for (int nt = 0; nt < 8; nt++) {
        const int col = h * HD + nt * 8 + tm4 * 2;
        float o00 = oacc[nt][0] * i0, o01 = oacc[nt][1] * i0;
        float o10 = oacc[nt][2] * i1, o11 = oacc[nt][3] * i1;
        float h00 = bf16round(o00), h01 = bf16round(o01);
        float h10 = bf16round(o10), h11 = bf16round(o11);
        ((uint32_t*)ctxh)[(r0 + col) >> 1] = pack_bf16(h00, h01);
        ((uint32_t*)ctxl)[(r0 + col) >> 1] = pack_bf16(o00 - h00, o01 - h01);
        ((uint32_t*)ctxh)[(r1 + col) >> 1] = pack_bf16(h10, h11);
        ((uint32_t*)ctxl)[(r1 + col) >> 1] = pack_bf16(o10 - h10, o11 - h11);
    }
}

// ---------------------------------------------------------------------------
extern "C" void kernel_launch(void* const* d_in, const int* in_sizes, int n_in,
                              void* d_out, int out_size) {
    const float* x     = (const float*)d_in[0];
    const float* Wqkv  = (const float*)d_in[1];
    const float* qscl  = (const float*)d_in[2];
    const float* kscl  = (const float*)d_in[3];
    const float* Wout  = (const float*)d_in[4];
    float* out = (float*)d_out;

    float* qkv;
    __nv_bfloat16 *xh, *xl, *wqh, *wql, *woh, *wol, *cth, *ctl;
    uint32_t *kph, *kpl, *vth, *vtl;
    cudaGetSymbolAddress((void**)&qkv, g_qkv);
    cudaGetSymbolAddress((void**)&xh,  g_xh);
    cudaGetSymbolAddress((void**)&xl,  g_xl);
    cudaGetSymbolAddress((void**)&wqh, g_wqh);
    cudaGetSymbolAddress((void**)&wql, g_wql);
    cudaGetSymbolAddress((void**)&woh, g_woh);
    cudaGetSymbolAddress((void**)&wol, g_wol);
    cudaGetSymbolAddress((void**)&cth, g_cth);
    cudaGetSymbolAddress((void**)&ctl, g_ctl);
    cudaGetSymbolAddress((void**)&kph, g_kph);
    cudaGetSymbolAddress((void**)&kpl, g_kpl);
    cudaGetSymbolAddress((void**)&vth, g_vth);
    cudaGetSymbolAddress((void**)&vtl, g_vtl);

    cudaFuncSetAttribute(gemm_bf16x3_kernel,
                         cudaFuncAttributeMaxDynamicSharedMemorySize, GEMM_SMEM_BYTES);
    cudaFuncSetAttribute(attn_bf16_kernel,
                         cudaFuncAttributeMaxDynamicSharedMemorySize, ATTN_SMEM_BYTES);

    // 0) splits: x elementwise; weights transpose+split
    {
        int n4x = ROWS * D_MODEL / 4;
        xsplit_kernel<<<(n4x + 255) / 256, 256>>>(x, xh, xl, n4x);
        dim3 gq(QKV_N / 32, D_MODEL / 32);
        trsplit_kernel<<<gq, 256>>>(Wqkv, wqh, wql, D_MODEL, QKV_N);
        dim3 go(D_MODEL / 32, D_MODEL / 32);
        trsplit_kernel<<<go, 256>>>(Wout, woh, wol, D_MODEL, D_MODEL);
    }
    // 1) qkv = x @ W_qkv   (3xBF16)
    {
        dim3 grid(QKV_N / BN, ROWS / BM);
        gemm_bf16x3_kernel<<<grid, 256, GEMM_SMEM_BYTES>>>(
            xh, xl, wqh, wql, qkv, ROWS, QKV_N, D_MODEL);
    }
    // 2) LN (q fp32 in place, k -> bf16 planes); V^T split
    {
        dim3 grid(ROWS, 2);
        ln_kernel<<<grid, 256>>>(qkv, qscl, kscl, kph, kpl);
        dim3 gv(SEQ / 32, HD / 32, BATCH * N_HEADS);
        vtsplit_kernel<<<gv, 256>>>(qkv, vth, vtl);
    }
    // 3) causal flash attention (all-bf16x3, 128-row tiles) -> ctx planes
    {
        dim3 grid(SEQ / 128, N_HEADS, BATCH);
        attn_bf16_kernel<<<grid, 256, ATTN_SMEM_BYTES>>>(
            qkv, kph, kpl, vth, vtl, cth, ctl);
    }
    // 4) out = ctx @ W_out  (3xBF16)
    {
        dim3 grid(D_MODEL / BN, ROWS / BM);
        gemm_bf16x3_kernel<<<grid, 256, GEMM_SMEM_BYTES>>>(
            cth, ctl, woh, wol, out, ROWS, D_MODEL, D_MODEL);
    }
}

// round 17
// speedup vs baseline: 1.0667x; 1.0667x over previous
#include <cuda_runtime.h>
#include <cuda_bf16.h>
#include <math.h>
#include <cstdint>

#define D_MODEL 1024
#define N_HEADS 16
#define HD      64
#define BATCH   2
#define SEQ     2048
#define ROWS    (BATCH*SEQ)      // 4096
#define QKV_N   (3*D_MODEL)      // 3072
#define LN_EPS  1e-6f

// Scratch (device-global: no runtime allocation allowed)
__device__ float g_qkv[(size_t)ROWS * QKV_N];              // 48 MB fp32 qkv
// bf16 hi/lo planes for GEMMs. Activations [M][K]; weights TRANSPOSED [N][K].
__device__ __nv_bfloat16 g_xh[(size_t)ROWS * D_MODEL];
__device__ __nv_bfloat16 g_xl[(size_t)ROWS * D_MODEL];
__device__ __nv_bfloat16 g_wqh[(size_t)QKV_N * D_MODEL];
__device__ __nv_bfloat16 g_wql[(size_t)QKV_N * D_MODEL];
__device__ __nv_bfloat16 g_woh[(size_t)D_MODEL * D_MODEL];
__device__ __nv_bfloat16 g_wol[(size_t)D_MODEL * D_MODEL];
__device__ __nv_bfloat16 g_cth[(size_t)ROWS * D_MODEL];    // ctx planes
__device__ __nv_bfloat16 g_ctl[(size_t)ROWS * D_MODEL];
// attention operand planes (bf16, packed as u32 pairs)
__device__ uint32_t g_kph[(size_t)ROWS * D_MODEL / 2];     // K post-LN hi
__device__ uint32_t g_kpl[(size_t)ROWS * D_MODEL / 2];     // K post-LN lo
__device__ uint32_t g_vth[(size_t)ROWS * D_MODEL / 2];     // V^T hi  [b,h][d][s]
__device__ uint32_t g_vtl[(size_t)ROWS * D_MODEL / 2];     // V^T lo

__device__ __forceinline__ uint32_t smem_u32(const void* p) {
    return (uint32_t)__cvta_generic_to_shared(p);
}

__device__ __forceinline__ void mma_bf16(float* d, const uint32_t* a, const uint32_t* b) {
    asm volatile(
        "mma.sync.aligned.m16n8k16.row.col.f32.bf16.bf16.f32 "
        "{%0,%1,%2,%3}, {%4,%5,%6,%7}, {%8,%9}, {%0,%1,%2,%3};\n"
        : "+f"(d[0]), "+f"(d[1]), "+f"(d[2]), "+f"(d[3])
        : "r"(a[0]), "r"(a[1]), "r"(a[2]), "r"(a[3]), "r"(b[0]), "r"(b[1]));
}
__device__ __forceinline__ float bf16round(float x) {
    return __bfloat162float(__float2bfloat16_rn(x));
}
__device__ __forceinline__ uint32_t pack_bf16(float a, float b) {
    uint16_t ua = __bfloat16_as_ushort(__float2bfloat16_rn(a));
    uint16_t ub = __bfloat16_as_ushort(__float2bfloat16_rn(b));
    return (uint32_t)ua | ((uint32_t)ub << 16);
}

// ---------------------------------------------------------------------------
// Activation split: X fp32 [M][K] -> bf16 hi/lo planes. 4 elems/thread.
// ---------------------------------------------------------------------------
__global__ __launch_bounds__(256)
void xsplit_kernel(const float* __restrict__ X, __nv_bfloat16* __restrict__ Xh,
                   __nv_bfloat16* __restrict__ Xl, int n4) {
    int i = blockIdx.x * blockDim.x + threadIdx.x;
    if (i >= n4) return;
    float4 v = ((const float4*)X)[i];
    float hx = bf16round(v.x), hy = bf16round(v.y);
    float hz = bf16round(v.z), hw = bf16round(v.w);
    uint32_t* H = (uint32_t*)Xh;
    uint32_t* L = (uint32_t*)Xl;
    H[2 * i]     = pack_bf16(hx, hy);
    H[2 * i + 1] = pack_bf16(hz, hw);
    L[2 * i]     = pack_bf16(v.x - hx, v.y - hy);
    L[2 * i + 1] = pack_bf16(v.z - hz, v.w - hw);
}

// ---------------------------------------------------------------------------
// Weight transpose + split: W fp32 [Kd][Nd] -> Th/Tl bf16 [Nd][Kd].
// ---------------------------------------------------------------------------
__global__ __launch_bounds__(256)
void trsplit_kernel(const float* __restrict__ W, __nv_bfloat16* __restrict__ Th,
                    __nv_bfloat16* __restrict__ Tl, int Kd, int Nd) {
    __shared__ float T[32][33];
    const int tid = threadIdx.x;
    const int tx = tid & 31, ty = tid >> 5;
    const int k0 = blockIdx.y * 32, n0 = blockIdx.x * 32;
#pragma unroll
    for (int r = 0; r < 4; r++)
        T[ty + r * 8][tx] = W[(size_t)(k0 + ty + r * 8) * Nd + n0 + tx];
    __syncthreads();
#pragma unroll
    for (int i = 0; i < 2; i++) {
        int idx = tid + i * 256;
        int nl = idx >> 4, kp = idx & 15;
        float v0 = T[kp * 2][nl], v1 = T[kp * 2 + 1][nl];
        float h0 = bf16round(v0), h1 = bf16round(v1);
        size_t e = (size_t)(n0 + nl) * Kd + k0 + kp * 2;
        ((uint32_t*)Th)[e >> 1] = pack_bf16(h0, h1);
        ((uint32_t*)Tl)[e >> 1] = pack_bf16(v0 - h0, v1 - h1);
    }
}

// ---------------------------------------------------------------------------
// V transpose + split: qkv v-slice -> VT planes [(b*16+h)*64+d][s] bf16 hi/lo.
// ---------------------------------------------------------------------------
__global__ __launch_bounds__(256)
void vtsplit_kernel(const float* __restrict__ qkv,
                    uint32_t* __restrict__ VTh, uint32_t* __restrict__ VTl) {
    __shared__ float T[32][33];
    const int tid = threadIdx.x;
    const int s0 = blockIdx.x * 32;
    const int d0 = blockIdx.y * 32;
    const int bh = blockIdx.z;
    const int b  = bh / N_HEADS;
    const int h  = bh % N_HEADS;
    const int tx = tid & 31, ty = tid >> 5;
#pragma unroll
    for (int r = 0; r < 4; r++) {
        int si = ty + r * 8;
        T[si][tx] = qkv[((size_t)(b * SEQ + s0 + si)) * QKV_N + 2 * D_MODEL + h * HD + d0 + tx];
    }
    __syncthreads();
#pragma unroll
    for (int i = 0; i < 2; i++) {
        int idx = tid + i * 256;           // 0..511
        int dl = idx >> 4, sp = idx & 15;
        float v0 = T[sp * 2][dl], v1 = T[sp * 2 + 1][dl];
        float h0 = bf16round(v0), h1 = bf16round(v1);
        size_t u = (size_t)(bh * HD + d0 + dl) * (SEQ / 2) + (s0 >> 1) + sp;
        VTh[u] = pack_bf16(h0, h1);
        VTl[u] = pack_bf16(v0 - h0, v1 - h1);
    }
}

// ===========================================================================
// 3xBF16 GEMM, BM=128 variant (validated R11/R13) — used for out-proj.
// ===========================================================================
#define BM 128
#define BN 128
#define BKE 32
#define RSTR 20
#define PLANE (128 * RSTR)
#define OFF_AL PLANE
#define OFF_BH (2 * PLANE)
#define OFF_BL (3 * PLANE)
#define STAGE_U32 (4 * PLANE)
#define GEMM_SMEM_BYTES (2 * STAGE_U32 * 4)   // 81920

__global__ __launch_bounds__(256, 2)
void gemm_bf16x3_kernel(const __nv_bfloat16* __restrict__ Ah, const __nv_bfloat16* __restrict__ Al,
                        const __nv_bfloat16* __restrict__ Bh, const __nv_bfloat16* __restrict__ Bl,
                        float* __restrict__ C, int M, int N, int K) {
    extern __shared__ uint32_t smu[];

    const int tid  = threadIdx.x;
    const int lane = tid & 31;
    const int warp = tid >> 5;
    const int warp_m = warp & 1;
    const int warp_n = warp >> 1;
    const int t4  = lane >> 2;
    const int tm4 = lane & 3;
    const int bm = blockIdx.y * BM;
    const int bn = blockIdx.x * BN;

    float acc[4][4][4];
#pragma unroll
    for (int mt = 0; mt < 4; mt++)
#pragma unroll
        for (int nt = 0; nt < 4; nt++)
#pragma unroll
            for (int r = 0; r < 4; r++) acc[mt][nt][r] = 0.f;

    const int nk = K / BKE;

    auto prefetch = [&](int buf, int kt) {
        const int k0 = kt * BKE;
        const int sb = buf * STAGE_U32;
#pragma unroll
        for (int l = 0; l < 4; l++) {
            int c = tid + l * 256;
            int plane = c >> 9, cc = c & 511;
            int m = cc >> 2, ch = cc & 3;
            const __nv_bfloat16* src = (plane ? Al : Ah) + (size_t)(bm + m) * K + k0 + ch * 8;
            uint32_t dst = smem_u32(&smu[sb + (plane ? OFF_AL : 0) + m * RSTR + ch * 4]);
            asm volatile("cp.async.cg.shared.global [%0], [%1], 16;\n"
                         :: "r"(dst), "l"(src));
        }
#pragma unroll
        for (int l = 0; l < 4; l++) {
            int c = tid + l * 256;
            int plane = c >> 9, cc = c & 511;
            int n = cc >> 2, ch = cc & 3;
            const __nv_bfloat16* src = (plane ? Bl : Bh) + (size_t)(bn + n) * K + k0 + ch * 8;
            uint32_t dst = smem_u32(&smu[sb + (plane ? OFF_BL : OFF_BH) + n * RSTR + ch * 4]);
            asm volatile("cp.async.cg.shared.global [%0], [%1], 16;\n"
                         :: "r"(dst), "l"(src));
        }
        asm volatile("cp.async.commit_group;\n");
    };

    prefetch(0, 0);

    for (int kt = 0; kt < nk; kt++) {
        const int buf = kt & 1;
        if (kt + 1 < nk) {
            prefetch(buf ^ 1, kt + 1);
            asm volatile("cp.async.wait_group 1;\n");
        } else {
            asm volatile("cp.async.wait_group 0;\n");
        }
        __syncthreads();

        const uint32_t* AhU = smu + buf * STAGE_U32;
        const uint32_t* AlU = AhU + OFF_AL;
        const uint32_t* BhU = AhU + OFF_BH;
        const uint32_t* BlU = AhU + OFF_BL;

#pragma unroll
        for (int ks = 0; ks < 2; ks++) {
            const int k0u = ks * 8;
            uint32_t ah[4][4], al[4][4];
#pragma unroll
            for (int mt = 0; mt < 4; mt++) {
                const int rb = warp_m * 64 + mt * 16;
                const int i0 = (rb + t4)     * RSTR + k0u + tm4;
                const int i1 = (rb + 8 + t4) * RSTR + k0u + tm4;
                ah[mt][0] = AhU[i0];     al[mt][0] = AlU[i0];
                ah[mt][1] = AhU[i1];     al[mt][1] = AlU[i1];
                ah[mt][2] = AhU[i0 + 4]; al[mt][2] = AlU[i0 + 4];
                ah[mt][3] = AhU[i1 + 4]; al[mt][3] = AlU[i1 + 4];
            }
            uint32_t bh[4][2], bl[4][2];
#pragma unroll
            for (int nt = 0; nt < 4; nt++) {
                const int nb = warp_n * 32 + nt * 8;
                const int i0 = (nb + t4) * RSTR + k0u + tm4;
                bh[nt][0] = BhU[i0];     bl[nt][0] = BlU[i0];
                bh[nt][1] = BhU[i0 + 4]; bl[nt][1] = BlU[i0 + 4];
            }
#pragma unroll
            for (int mt = 0; mt < 4; mt++)
#pragma unroll
                for (int nt = 0; nt < 4; nt++) {
                    mma_bf16(acc[mt][nt], al[mt], bh[nt]);
                    mma_bf16(acc[mt][nt], ah[mt], bl[nt]);
                    mma_bf16(acc[mt][nt], ah[mt], bh[nt]);
                }
        }
        __syncthreads();
    }

#pragma unroll
    for (int mt = 0; mt < 4; mt++) {
#pragma unroll
        for (int nt = 0; nt < 4; nt++) {
            const int row = bm + warp_m * 64 + mt * 16 + t4;
            const int col = bn + warp_n * 32 + nt * 8 + tm4 * 2;
            float2 v0 = make_float2(acc[mt][nt][0], acc[mt][nt][1]);
            float2 v1 = make_float2(acc[mt][nt][2], acc[mt][nt][3]);
            *(float2*)&C[(size_t)row * N + col]       = v0;
            *(float2*)&C[(size_t)(row + 8) * N + col] = v1;
        }
    }
}

// ===========================================================================
// 3xBF16 GEMM, BM=64 high-occupancy variant — used for QKV.
// 64x128 CTA tile, 256 thr = 8 warps (2m x 4n), warp tile 32x32.
// ~64 live acc+frag regs -> 3 CTAs/SM (24 warps) for latency hiding.
// Smem/stage: Ah 64x20 | Al 64x20 | Bh 128x20 | Bl 128x20 u32 = 30720 B.
// ===========================================================================
#define A64_PL (64 * RSTR)                 // 1280 u32
#define B64_PL (128 * RSTR)                // 2560 u32
#define O64_AL A64_PL
#define O64_BH (2 * A64_PL)
#define O64_BL (2 * A64_PL + B64_PL)
#define STG64  (2 * A64_PL + 2 * B64_PL)   // 7680 u32
#define GEMM64_SMEM_BYTES (2 * STG64 * 4)  // 61440

__global__ __launch_bounds__(256, 3)
void gemm_bf16x3_k64(const __nv_bfloat16* __restrict__ Ah, const __nv_bfloat16* __restrict__ Al,
                     const __nv_bfloat16* __restrict__ Bh, const __nv_bfloat16* __restrict__ Bl,
                     float* __restrict__ C, int M, int N, int K) {
    extern __shared__ uint32_t smu[];

    const int tid  = threadIdx.x;
    const int lane = tid & 31;
    const int warp = tid >> 5;
    const int warp_m = warp & 1;     // 2 m-groups of 32 rows
    const int warp_n = warp >> 1;    // 4 n-groups of 32 cols
    const int t4  = lane >> 2;
    const int tm4 = lane & 3;
    const int bm = blockIdx.y * 64;
    const int bn = blockIdx.x * 128;

    float acc[2][4][4];
#pragma unroll
    for (int mt = 0; mt < 2; mt++)
#pragma unroll
        for (int nt = 0; nt < 4; nt++)
#pragma unroll
            for (int r = 0; r < 4; r++) acc[mt][nt][r] = 0.f;

    const int nk = K / BKE;

    auto prefetch = [&](int buf, int kt) {
        const int k0 = kt * BKE;
        const int sb = buf * STG64;
        // A planes: 64 rows x 4 chunks x 2 planes = 512 chunks, 2/thread
#pragma unroll
        for (int l = 0; l < 2; l++) {
            int c = tid + l * 256;
            int plane = c >> 8, cc = c & 255;
            int m = cc >> 2, ch = cc & 3;
            const __nv_bfloat16* src = (plane ? Al : Ah) + (size_t)(bm + m) * K + k0 + ch * 8;
            uint32_t dst = smem_u32(&smu[sb + (plane ? O64_AL : 0) + m * RSTR + ch * 4]);
            asm volatile("cp.async.cg.shared.global [%0], [%1], 16;\n"
                         :: "r"(dst), "l"(src));
        }
        // B planes: 128 rows x 4 chunks x 2 planes = 1024 chunks, 4/thread
#pragma unroll
        for (int l = 0; l < 4; l++) {
            int c = tid + l * 256;
            int plane = c >> 9, cc = c & 511;
            int n = cc >> 2, ch = cc & 3;
            const __nv_bfloat16* src = (plane ? Bl : Bh) + (size_t)(bn + n) * K + k0 + ch * 8;
            uint32_t dst = smem_u32(&smu[sb + (plane ? O64_BL : O64_BH) + n * RSTR + ch * 4]);
            asm volatile("cp.async.cg.shared.global [%0], [%1], 16;\n"
                         :: "r"(dst), "l"(src));
        }
        asm volatile("cp.async.commit_group;\n");
    };

    prefetch(0, 0);

    for (int kt = 0; kt < nk; kt++) {
        const int buf = kt & 1;
        if (kt + 1 < nk) {
            prefetch(buf ^ 1, kt + 1);
            asm volatile("cp.async.wait_group 1;\n");
        } else {
            asm volatile("cp.async.wait_group 0;\n");
        }
        __syncthreads();

        const uint32_t* AhU = smu + buf * STG64;
        const uint32_t* AlU = AhU + O64_AL;
        const uint32_t* BhU = AhU + O64_BH;
        const uint32_t* BlU = AhU + O64_BL;

#pragma unroll
        for (int ks = 0; ks < 2; ks++) {
            const int k0u = ks * 8;
            uint32_t ah[2][4], al[2][4];
#pragma unroll
            for (int mt = 0; mt < 2; mt++) {
                const int rb = warp_m * 32 + mt * 16;
                const int i0 = (rb + t4)     * RSTR + k0u + tm4;
                const int i1 = (rb + 8 + t4) * RSTR + k0u + tm4;
                ah[mt][0] = AhU[i0];     al[mt][0] = AlU[i0];
                ah[mt][1] = AhU[i1];     al[mt][1] = AlU[i1];
                ah[mt][2] = AhU[i0 + 4]; al[mt][2] = AlU[i0 + 4];
                ah[mt][3] = AhU[i1 + 4]; al[mt][3] = AlU[i1 + 4];
            }
            uint32_t bh[4][2], bl[4][2];
#pragma unroll
            for (int nt = 0; nt < 4; nt++) {
                const int nb = warp_n * 32 + nt * 8;
                const int i0 = (nb + t4) * RSTR + k0u + tm4;
                bh[nt][0] = BhU[i0];     bl[nt][0] = BlU[i0];
                bh[nt][1] = BhU[i0 + 4]; bl[nt][1] = BlU[i0 + 4];
            }
#pragma unroll
            for (int mt = 0; mt < 2; mt++)
#pragma unroll
                for (int nt = 0; nt < 4; nt++) {
                    mma_bf16(acc[mt][nt], al[mt], bh[nt]);
                    mma_bf16(acc[mt][nt], ah[mt], bl[nt]);
                    mma_bf16(acc[mt][nt], ah[mt], bh[nt]);
                }
        }
        __syncthreads();
    }

#pragma unroll
    for (int mt = 0; mt < 2; mt++) {
#pragma unroll
        for (int nt = 0; nt < 4; nt++) {
            const int row = bm + warp_m * 32 + mt * 16 + t4;
            const int col = bn + warp_n * 32 + nt * 8 + tm4 * 2;
            float2 v0 = make_float2(acc[mt][nt][0], acc[mt][nt][1]);
            float2 v1 = make_float2(acc[mt][nt][2], acc[mt][nt][3]);
            *(float2*)&C[(size_t)row * N + col]       = v0;
            *(float2*)&C[(size_t)(row + 8) * N + col] = v1;
        }
    }
}

// ---------------------------------------------------------------------------
// LayerNorm (scale-only). which=0: q normalized fp32 in place.
// which=1: k -> pre-split bf16 hi/lo planes (u32 packed).
// ---------------------------------------------------------------------------
__global__ __launch_bounds__(256)
void ln_kernel(float* __restrict__ qkv, const float* __restrict__ q_scale,
               const float* __restrict__ k_scale,
               uint32_t* __restrict__ kh, uint32_t* __restrict__ kl) {
    const int row = blockIdx.x;
    const int which = blockIdx.y;
    const float* scale = which ? k_scale : q_scale;
    float* ptr = qkv + (size_t)row * QKV_N + which * D_MODEL;

    const int tid = threadIdx.x;
    float4 v = ((const float4*)ptr)[tid];
    float sum = v.x + v.y + v.z + v.w;
    float sq  = v.x * v.x + v.y * v.y + v.z * v.z + v.w * v.w;
#pragma unroll
    for (int o = 16; o > 0; o >>= 1) {
        sum += __shfl_xor_sync(0xffffffffu, sum, o);
        sq  += __shfl_xor_sync(0xffffffffu, sq,  o);
    }
    __shared__ float ssum[8], ssq[8];
    const int warp = tid >> 5, lane = tid & 31;
    if (lane == 0) { ssum[warp] = sum; ssq[warp] = sq; }
    __syncthreads();
    if (tid == 0) {
        float a = 0.f, bsum = 0.f;
#pragma unroll
        for (int w = 0; w < 8; w++) { a += ssum[w]; bsum += ssq[w]; }
        ssum[0] = a; ssq[0] = bsum;
    }
    __syncthreads();
    const float mean = ssum[0] * (1.f / D_MODEL);
    const float var  = ssq[0] * (1.f / D_MODEL) - mean * mean;
    const float inv  = rsqrtf(var + LN_EPS);

    const int c = tid * 4;
    float n0 = (v.x - mean) * inv * scale[c];
    float n1 = (v.y - mean) * inv * scale[c + 1];
    float n2 = (v.z - mean) * inv * scale[c + 2];
    float n3 = (v.w - mean) * inv * scale[c + 3];
    if (which == 0) {
        ((float4*)ptr)[tid] = make_float4(n0, n1, n2, n3);
    } else {
        float h0 = bf16round(n0), h1 = bf16round(n1);
        float h2 = bf16round(n2), h3 = bf16round(n3);
        size_t u = (size_t)row * (D_MODEL / 2) + tid * 2;
        kh[u]     = pack_bf16(h0, h1);
        kh[u + 1] = pack_bf16(h2, h3);
        kl[u]     = pack_bf16(n0 - h0, n1 - h1);
        kl[u + 1] = pack_bf16(n2 - h2, n3 - h3);
    }
}

// ===========================================================================
// Flash attention, all-bf16x3 tensor core (validated R13). Causal.
// 64-q-row tiles, 128 thr, 2 CTAs/SM. qt reversed: heavy tiles first.
// ===========================================================================
#define KSTR 36                   // u32 per 64-bf16 row (+4 pad)
#define APLANE (64 * KSTR)        // 2304 u32
#define OFF_K  4608
#define OFF_VT 13824
#define ATTN_SMEM_BYTES (23040 * 4)   // 92160

__global__ __launch_bounds__(128)
void attn_bf16_kernel(const float* __restrict__ qkv,
                      const uint32_t* __restrict__ Kh, const uint32_t* __restrict__ Kl,
                      const uint32_t* __restrict__ VTh, const uint32_t* __restrict__ VTl,
                      __nv_bfloat16* __restrict__ ctxh, __nv_bfloat16* __restrict__ ctxl) {
    extern __shared__ uint32_t smu[];
    uint32_t* Ph = smu;
    uint32_t* Pl = smu + APLANE;

    const int qt = gridDim.x - 1 - blockIdx.x;   // heavy diagonal tiles first
    const int h  = blockIdx.y;
    const int b  = blockIdx.z;
    const int tid  = threadIdx.x;
    const int lane = tid & 31;
    const int w    = tid >> 5;
    const int t4   = lane >> 2;
    const int tm4  = lane & 3;
    const int w16  = w * 16;

    auto prefetch_kv = [&](int buf, int kt) {
        const size_t kgo = ((size_t)(b * SEQ + kt * 64) * D_MODEL + h * HD) / 2;
        const size_t vgo = ((size_t)((b * N_HEADS + h) * HD) * SEQ + (size_t)kt * 64) / 2;
        uint32_t* kd = smu + OFF_K + buf * 2 * APLANE;
        uint32_t* vd = smu + OFF_VT + buf * 2 * APLANE;
#pragma unroll
        for (int l = 0; l < 4; l++) {
            int c = tid + l * 128;          // 0..511
            int row = c >> 3, ch = c & 7;
            asm volatile("cp.async.cg.shared.global [%0], [%1], 16;\n"
                :: "r"(smem_u32(&kd[row * KSTR + ch * 4])), "l"(Kh + kgo + (size_t)row * 512 + ch * 4));
            asm volatile("cp.async.cg.shared.global [%0], [%1], 16;\n"
                :: "r"(smem_u32(&kd[APLANE + row * KSTR + ch * 4])), "l"(Kl + kgo + (size_t)row * 512 + ch * 4));
            asm volatile("cp.async.cg.shared.global [%0], [%1], 16;\n"
                :: "r"(smem_u32(&vd[row * KSTR + ch * 4])), "l"(VTh + vgo + (size_t)row * 1024 + ch * 4));
            asm volatile("cp.async.cg.shared.global [%0], [%1], 16;\n"
                :: "r"(smem_u32(&vd[APLANE + row * KSTR + ch * 4])), "l"(VTl + vgo + (size_t)row * 1024 + ch * 4));
        }
        asm volatile("cp.async.commit_group;\n");
    };

    prefetch_kv(0, 0);

    // stage Q fp32 in the P area (stride 68 floats), then build register frags
    {
        float* Qs = (float*)smu;
        const float* qbase = qkv + ((size_t)(b * SEQ + qt * 64)) * QKV_N + (size_t)h * HD;
#pragma unroll
        for (int l = 0; l < 8; l++) {
            int c = tid + l * 128;
            int row = c >> 4, c4 = c & 15;
            float4 v = *(const float4*)(qbase + (size_t)row * QKV_N + c4 * 4);
            *(float4*)&Qs[row * 68 + c4 * 4] = v;
        }
    }
    __syncthreads();

    uint32_t qah[4][4], qal[4][4];
    {
        const float* Qs = (const float*)smu;
#pragma unroll
        for (int ks = 0; ks < 4; ks++) {
            const int j0 = ks * 8 + tm4;
#pragma unroll
            for (int p = 0; p < 4; p++) {
                const int r = w16 + t4 + ((p & 1) ? 8 : 0);
                const int j = j0 + ((p >> 1) ? 4 : 0);
                float v0 = 0.125f * Qs[r * 68 + 2 * j];
                float v1 = 0.125f * Qs[r * 68 + 2 * j + 1];
                float h0 = bf16round(v0), h1 = bf16round(v1);
                qah[ks][p] = pack_bf16(h0, h1);
                qal[ks][p] = pack_bf16(v0 - h0, v1 - h1);
            }
        }
    }
    __syncthreads();   // Q staging done; P area free

    float m0 = -1e30f, m1 = -1e30f, l0 = 0.f, l1 = 0.f;
    float oacc[8][4];
#pragma unroll
    for (int nt = 0; nt < 8; nt++)
#pragma unroll
        for (int r = 0; r < 4; r++) oacc[nt][r] = 0.f;

    for (int kt = 0; kt <= qt; kt++) {
        const int buf = kt & 1;
        asm volatile("cp.async.wait_group 0;\n");
        __syncthreads();
        if (kt < qt) prefetch_kv(buf ^ 1, kt + 1);

        const uint32_t* KbH = smu + OFF_K + buf * 2 * APLANE;
        const uint32_t* KbL = KbH + APLANE;
        const uint32_t* VbH = smu + OFF_VT + buf * 2 * APLANE;
        const uint32_t* VbL = VbH + APLANE;

        // ---- S = (Q*0.125) @ K^T  (3xBF16, m16n8k16, 4 k-steps) ----
        float s[8][4];
#pragma unroll
        for (int nt = 0; nt < 8; nt++)
#pragma unroll
            for (int r = 0; r < 4; r++) s[nt][r] = 0.f;

#pragma unroll
        for (int ks = 0; ks < 4; ks++) {
            const int k0u = ks * 8;
            uint32_t bh[8][2], bl[8][2];
#pragma unroll
            for (int nt = 0; nt < 8; nt++) {
                const int i0 = (nt * 8 + t4) * KSTR + k0u + tm4;
                bh[nt][0] = KbH[i0];     bl[nt][0] = KbL[i0];
                bh[nt][1] = KbH[i0 + 4]; bl[nt][1] = KbL[i0 + 4];
            }
#pragma unroll
            for (int nt = 0; nt < 8; nt++) {
                mma_bf16(s[nt], qal[ks], bh[nt]);
                mma_bf16(s[nt], qah[ks], bl[nt]);
                mma_bf16(s[nt], qah[ks], bh[nt]);
            }
        }

        if (kt == qt) {
#pragma unroll
            for (int nt = 0; nt < 8; nt++) {
                const int c0 = nt * 8 + tm4 * 2;
                const int r0 = w16 + t4;
                if (c0     > r0)     s[nt][0] = -1e30f;
                if (c0 + 1 > r0)     s[nt][1] = -1e30f;
                if (c0     > r0 + 8) s[nt][2] = -1e30f;
                if (c0 + 1 > r0 + 8) s[nt][3] = -1e30f;
            }
        }

        // ---- online softmax (fp32 exact) ----
        float rm0 = -1e30f, rm1 = -1e30f;
#pragma unroll
        for (int nt = 0; nt < 8; nt++) {
            rm0 = fmaxf(rm0, fmaxf(s[nt][0], s[nt][1]));
            rm1 = fmaxf(rm1, fmaxf(s[nt][2], s[nt][3]));
        }
#pragma unroll
        for (int o = 1; o <= 2; o <<= 1) {
            rm0 = fmaxf(rm0, __shfl_xor_sync(0xffffffffu, rm0, o));
            rm1 = fmaxf(rm1, __shfl_xor_sync(0xffffffffu, rm1, o));
        }
        const float nm0 = fmaxf(m0, rm0);
        const float nm1 = fmaxf(m1, rm1);
        const float c0 = expf(m0 - nm0);
        const float c1 = expf(m1 - nm1);
        float rs0 = 0.f, rs1 = 0.f;
#pragma unroll
        for (int nt = 0; nt < 8; nt++) {
            s[nt][0] = expf(s[nt][0] - nm0);
            s[nt][1] = expf(s[nt][1] - nm0);
            s[nt][2] = expf(s[nt][2] - nm1);
            s[nt][3] = expf(s[nt][3] - nm1);
            rs0 += s[nt][0] + s[nt][1];
            rs1 += s[nt][2] + s[nt][3];
        }
#pragma unroll
        for (int o = 1; o <= 2; o <<= 1) {
            rs0 += __shfl_xor_sync(0xffffffffu, rs0, o);
            rs1 += __shfl_xor_sync(0xffffffffu, rs1, o);
        }
        l0 = l0 * c0 + rs0;  m0 = nm0;
        l1 = l1 * c1 + rs1;  m1 = nm1;
#pragma unroll
        for (int nt = 0; nt < 8; nt++) {
            oacc[nt][0] *= c0; oacc[nt][1] *= c0;
            oacc[nt][2] *= c1; oacc[nt][3] *= c1;
        }

        // ---- P split hi/lo, packed STS ----
#pragma unroll
        for (int nt = 0; nt < 8; nt++) {
            const int i0 = (w16 + t4)     * KSTR + nt * 4 + tm4;
            const int i1 = (w16 + t4 + 8) * KSTR + nt * 4 + tm4;
            float h0 = bf16round(s[nt][0]), h1 = bf16round(s[nt][1]);
            float h2 = bf16round(s[nt][2]), h3 = bf16round(s[nt][3]);
            Ph[i0] = pack_bf16(h0, h1);
            Pl[i0] = pack_bf16(s[nt][0] - h0, s[nt][1] - h1);
            Ph[i1] = pack_bf16(h2, h3);
            Pl[i1] = pack_bf16(s[nt][2] - h2, s[nt][3] - h3);
        }
        __syncwarp();

        // ---- O += P @ V^T  (3xBF16: pl*vh + ph*vl + ph*vh) ----
#pragma unroll
        for (int ks = 0; ks < 4; ks++) {
            const int j0 = ks * 8 + tm4;
            const int r0i = (w16 + t4) * KSTR;
            const int r1i = (w16 + t4 + 8) * KSTR;
            uint32_t pah[4], pal[4];
            pah[0] = Ph[r0i + j0];     pal[0] = Pl[r0i + j0];
            pah[1] = Ph[r1i + j0];     pal[1] = Pl[r1i + j0];
            pah[2] = Ph[r0i + j0 + 4]; pal[2] = Pl[r0i + j0 + 4];
            pah[3] = Ph[r1i + j0 + 4]; pal[3] = Pl[r1i + j0 + 4];
#pragma unroll
            for (int nt = 0; nt < 8; nt++) {
                const int i0 = (nt * 8 + t4) * KSTR + ks * 8 + tm4;
                uint32_t vh[2], vl[2];
                vh[0] = VbH[i0];     vl[0] = VbL[i0];
                vh[1] = VbH[i0 + 4]; vl[1] = VbL[i0 + 4];
                mma_bf16(oacc[nt], pal, vh);
                mma_bf16(oacc[nt], pah, vl);
                mma_bf16(oacc[nt], pah, vh);
            }
        }
        __syncwarp();
    }

    // epilogue: normalize, split to bf16 hi/lo ctx planes
    const float i0 = 1.f / l0, i1 = 1.f / l1;
    const size_t r0 = (size_t)(b * SEQ + qt * 64 + w16 + t4) * D_MODEL;
    const size_t r1 = (size_t)(b * SEQ + qt * 64 + w16 + t4 + 8) * D_MODEL;
#pragma unroll
    for (int nt = 0; nt < 8; nt++) {
        const int col = h * HD + nt * 8 + tm4 * 2;
        float o00 = oacc[nt][0] * i0, o01 = oacc[nt][1] * i0;
        float o10 = oacc[nt][2] * i1, o11 = oacc[nt][3] * i1;
        float h00 = bf16round(o00), h01 = bf16round(o01);
        float h10 = bf16round(o10), h11 = bf16round(o11);
        ((uint32_t*)ctxh)[(r0 + col) >> 1] = pack_bf16(h00, h01);
        ((uint32_t*)ctxl)[(r0 + col) >> 1] = pack_bf16(o00 - h00, o01 - h01);
        ((uint32_t*)ctxh)[(r1 + col) >> 1] = pack_bf16(h10, h11);
        ((uint32_t*)ctxl)[(r1 + col) >> 1] = pack_bf16(o10 - h10, o11 - h11);
    }
}

// ---------------------------------------------------------------------------
extern "C" void kernel_launch(void* const* d_in, const int* in_sizes, int n_in,
                              void* d_out, int out_size) {
    const float* x     = (const float*)d_in[0];
    const float* Wqkv  = (const float*)d_in[1];
    const float* qscl  = (const float*)d_in[2];
    const float* kscl  = (const float*)d_in[3];
    const float* Wout  = (const float*)d_in[4];
    float* out = (float*)d_out;

    float* qkv;
    __nv_bfloat16 *xh, *xl, *wqh, *wql, *woh, *wol, *cth, *ctl;
    uint32_t *kph, *kpl, *vth, *vtl;
    cudaGetSymbolAddress((void**)&qkv, g_qkv);
    cudaGetSymbolAddress((void**)&xh,  g_xh);
    cudaGetSymbolAddress((void**)&xl,  g_xl);
    cudaGetSymbolAddress((void**)&wqh, g_wqh);
    cudaGetSymbolAddress((void**)&wql, g_wql);
    cudaGetSymbolAddress((void**)&woh, g_woh);
    cudaGetSymbolAddress((void**)&wol, g_wol);
    cudaGetSymbolAddress((void**)&cth, g_cth);
    cudaGetSymbolAddress((void**)&ctl, g_ctl);
    cudaGetSymbolAddress((void**)&kph, g_kph);
    cudaGetSymbolAddress((void**)&kpl, g_kpl);
    cudaGetSymbolAddress((void**)&vth, g_vth);
    cudaGetSymbolAddress((void**)&vtl, g_vtl);

    cudaFuncSetAttribute(gemm_bf16x3_kernel,
                         cudaFuncAttributeMaxDynamicSharedMemorySize, GEMM_SMEM_BYTES);
    cudaFuncSetAttribute(gemm_bf16x3_k64,
                         cudaFuncAttributeMaxDynamicSharedMemorySize, GEMM64_SMEM_BYTES);
    cudaFuncSetAttribute(attn_bf16_kernel,
                         cudaFuncAttributeMaxDynamicSharedMemorySize, ATTN_SMEM_BYTES);

    // 0) splits: x elementwise; weights transpose+split
    {
        int n4x = ROWS * D_MODEL / 4;
        xsplit_kernel<<<(n4x + 255) / 256, 256>>>(x, xh, xl, n4x);
        dim3 gq(QKV_N / 32, D_MODEL / 32);
        trsplit_kernel<<<gq, 256>>>(Wqkv, wqh, wql, D_MODEL, QKV_N);
        dim3 go(D_MODEL / 32, D_MODEL / 32);
        trsplit_kernel<<<go, 256>>>(Wout, woh, wol, D_MODEL, D_MODEL);
    }
    // 1) qkv = x @ W_qkv   (3xBF16, high-occupancy BM=64 variant)
    {
        dim3 grid(QKV_N / 128, ROWS / 64);
        gemm_bf16x3_k64<<<grid, 256, GEMM64_SMEM_BYTES>>>(
            xh, xl, wqh, wql, qkv, ROWS, QKV_N, D_MODEL);
    }
    // 2) LN (q fp32 in place, k -> bf16 planes); V^T split
    {
        dim3 grid(ROWS, 2);
        ln_kernel<<<grid, 256>>>(qkv, qscl, kscl, kph, kpl);
        dim3 gv(SEQ / 32, HD / 32, BATCH * N_HEADS);
        vtsplit_kernel<<<gv, 256>>>(qkv, vth, vtl);
    }
    // 3) causal flash attention (all-bf16x3, 64-row tiles, heavy-first) -> ctx planes
    {
        dim3 grid(SEQ / 64, N_HEADS, BATCH);
        attn_bf16_kernel<<<grid, 128, ATTN_SMEM_BYTES>>>(
            qkv, kph, kpl, vth, vtl, cth, ctl);
    }
    // 4) out = ctx @ W_out  (3xBF16, BM=128 variant)
    {
        dim3 grid(D_MODEL / BN, ROWS / BM);
        gemm_bf16x3_kernel<<<grid, 256, GEMM_SMEM_BYTES>>>(
            cth, ctl, woh, wol, out, ROWS, D_MODEL, D_MODEL);
    }
}